// round 7
// baseline (speedup 1.0000x reference)
#include <cuda_runtime.h>
#include <cuda_bf16.h>

#define DD   64
#define LL   3
#define NMAX 100000
#define EMAX 1200000
#define WSTRIDE 80   // bf16 row stride; 64b B-loads conflict-free (bank pair = 4*grp+t mod 16)

// ---------------- scratch (device globals: allocation-free) ----------------
// g_cnt lifecycle: zero at module load; hist needs cnt==0; scan1 re-zeroes it
// after reading (scatter cursor); agg re-zeroes it for the next graph replay.
__device__ float g_M[NMAX * DD];
__device__ float g_G[NMAX * DD];
__device__ float g_H[NMAX * DD];
__device__ float g_H2[NMAX * DD];
__device__ int   g_cnt[NMAX];
__device__ int   g_rowptr[NMAX];     // within-block exclusive prefix
__device__ int   g_ecol[EMAX];
__device__ int   g_bsums[1024];      // per-block offsets (exclusive)

// ---------------- CSR construction (validated) ----------------
__global__ void hist_kernel(const int* __restrict__ rows, int E) {
    int e = blockIdx.x * blockDim.x + threadIdx.x;
    if (e < E) atomicAdd(&g_cnt[rows[e]], 1);
}

__global__ void scan1_kernel(int n) {
    __shared__ int sh[1024];
    int i = blockIdx.x * 1024 + threadIdx.x;
    int v = 0;
    if (i < n) { v = g_cnt[i]; g_cnt[i] = 0; }
    sh[threadIdx.x] = v;
    __syncthreads();
    for (int off = 1; off < 1024; off <<= 1) {
        int t = (threadIdx.x >= off) ? sh[threadIdx.x - off] : 0;
        __syncthreads();
        sh[threadIdx.x] += t;
        __syncthreads();
    }
    if (i < n) g_rowptr[i] = sh[threadIdx.x] - v;
    if (threadIdx.x == 1023) g_bsums[blockIdx.x] = sh[1023];
}

__global__ void scan2_kernel(int nb) {
    __shared__ int sh[1024];
    int v = (threadIdx.x < nb) ? g_bsums[threadIdx.x] : 0;
    sh[threadIdx.x] = v;
    __syncthreads();
    for (int off = 1; off < 1024; off <<= 1) {
        int t = (threadIdx.x >= off) ? sh[threadIdx.x - off] : 0;
        __syncthreads();
        sh[threadIdx.x] += t;
        __syncthreads();
    }
    if (threadIdx.x < nb) g_bsums[threadIdx.x] = sh[threadIdx.x] - v;
}

__global__ void scatter_kernel(const int* __restrict__ rows,
                               const int* __restrict__ cols, int E) {
    int e = blockIdx.x * blockDim.x + threadIdx.x;
    if (e < E) {
        int r = rows[e];
        int base = g_rowptr[r] + g_bsums[r >> 10];
        int pos = base + atomicAdd(&g_cnt[r], 1);
        g_ecol[pos] = cols[e];
    }
}

// ---------------- bf16 helpers ----------------
__device__ __forceinline__ unsigned packbf(float lo, float hi) {
    unsigned r;
    asm("cvt.rn.bf16x2.f32 %0, %1, %2;" : "=r"(r) : "f"(hi), "f"(lo));
    return r;
}
__device__ __forceinline__ float lo_f(unsigned u) { return __uint_as_float(u << 16); }
__device__ __forceinline__ float hi_f(unsigned u) { return __uint_as_float(u & 0xffff0000u); }

__device__ __forceinline__ void mma_bf16(float* d,
        unsigned a0, unsigned a1, unsigned a2, unsigned a3,
        unsigned b0, unsigned b1) {
    asm("mma.sync.aligned.m16n8k16.row.col.f32.bf16.bf16.f32 "
        "{%0,%1,%2,%3}, {%4,%5,%6,%7}, {%8,%9}, {%0,%1,%2,%3};"
        : "+f"(d[0]), "+f"(d[1]), "+f"(d[2]), "+f"(d[3])
        : "r"(a0), "r"(a1), "r"(a2), "r"(a3), "r"(b0), "r"(b1));
}

// ---------------- weight prep: W f32 [k][n] -> smem bf16 split, B-fragment order --
// Within row ncol (length 64 bf16): original k -> off = kb*16 + tg*4 + hi*2 + b
// where kb=k>>4, r=k&15, tg=(r&7)>>1, b=r&1, hi=r>>3. A thread's {b0,b1} pair
// for (kb,tig) then sits at one 8-byte-aligned 64-bit word.
__device__ __forceinline__ void prep_w(__nv_bfloat16* wh, __nv_bfloat16* wl,
                                       const float* __restrict__ W, int tid) {
    for (int idx = tid; idx < DD * DD; idx += 128) {
        int k = idx >> 6, nn = idx & 63;
        int kb = k >> 4, r = k & 15;
        int tg = (r & 7) >> 1, b = r & 1, hi = r >> 3;
        int off = nn * WSTRIDE + kb * 16 + tg * 4 + hi * 2 + b;
        float w = W[idx];
        __nv_bfloat16 h = __float2bfloat16(w);
        wh[off] = h;
        wl[off] = __float2bfloat16(w - __bfloat162float(h));
    }
}

// ---------------- one 16-row GEMM stage on tensor cores ----------------
// act[nb][q] C-fragment: q0=(grp,2t) q1=(grp,2t+1) q2=(grp+8,2t) q3=(grp+8,2t+1),
// cols nb*8+..; rows are warp-relative.
__device__ __forceinline__ void stage16(float (&act)[8][4],
        const __nv_bfloat16* wh, const __nv_bfloat16* wl,
        const float* bias, int lane, bool do_relu) {
    int tig = lane & 3, grp = lane >> 2;
    float acc[8][4];
    const float2* bp = (const float2*)bias;
#pragma unroll
    for (int nb = 0; nb < 8; nb++) {
        float2 bv = bp[nb * 4 + tig];
        acc[nb][0] = bv.x; acc[nb][1] = bv.y;
        acc[nb][2] = bv.x; acc[nb][3] = bv.y;
    }
#pragma unroll
    for (int kb = 0; kb < 4; kb++) {
        unsigned Ah[4], Al[4];
        const float* c0 = act[2 * kb];
        const float* c1 = act[2 * kb + 1];
        Ah[0] = packbf(c0[0], c0[1]);
        Ah[1] = packbf(c0[2], c0[3]);
        Ah[2] = packbf(c1[0], c1[1]);
        Ah[3] = packbf(c1[2], c1[3]);
        Al[0] = packbf(c0[0] - lo_f(Ah[0]), c0[1] - hi_f(Ah[0]));
        Al[1] = packbf(c0[2] - lo_f(Ah[1]), c0[3] - hi_f(Ah[1]));
        Al[2] = packbf(c1[0] - lo_f(Ah[2]), c1[1] - hi_f(Ah[2]));
        Al[3] = packbf(c1[2] - lo_f(Ah[3]), c1[3] - hi_f(Ah[3]));
        int woff = kb * 16 + tig * 4;
#pragma unroll
        for (int nb = 0; nb < 8; nb++) {
            int ncol = nb * 8 + grp;
            unsigned long long bh = *(const unsigned long long*)(wh + ncol * WSTRIDE + woff);
            unsigned long long bl = *(const unsigned long long*)(wl + ncol * WSTRIDE + woff);
            unsigned bh0 = (unsigned)bh, bh1 = (unsigned)(bh >> 32);
            unsigned bl0 = (unsigned)bl, bl1 = (unsigned)(bl >> 32);
            mma_bf16(acc[nb], Ah[0], Ah[1], Ah[2], Ah[3], bh0, bh1);
            mma_bf16(acc[nb], Al[0], Al[1], Al[2], Al[3], bh0, bh1);
            mma_bf16(acc[nb], Ah[0], Ah[1], Ah[2], Ah[3], bl0, bl1);
        }
    }
#pragma unroll
    for (int nb = 0; nb < 8; nb++)
#pragma unroll
        for (int q = 0; q < 4; q++)
            act[nb][q] = do_relu ? fmaxf(acc[nb][q], 0.0f) : acc[nb][q];
}

// ---- act <-> gmem (row-major [n][64]) in C-fragment layout ----
template <bool DO_ADD>
__device__ __forceinline__ void load_act16(float (&act)[8][4],
        const float* __restrict__ in, const float* __restrict__ addv,
        int wrow, int n, int lane) {
    int tig = lane & 3, grp = lane >> 2;
    int ra = wrow + grp, rb = ra + 8;
#pragma unroll
    for (int nb = 0; nb < 8; nb++) {
        int cw = nb * 4 + tig;
        float2 v = make_float2(0.f, 0.f), w = make_float2(0.f, 0.f);
        if (ra < n) {
            v = ((const float2*)(in + (size_t)ra * DD))[cw];
            if (DO_ADD) {
                float2 g = ((const float2*)(addv + (size_t)ra * DD))[cw];
                v.x += g.x; v.y += g.y;
            }
        }
        if (rb < n) {
            w = ((const float2*)(in + (size_t)rb * DD))[cw];
            if (DO_ADD) {
                float2 g = ((const float2*)(addv + (size_t)rb * DD))[cw];
                w.x += g.x; w.y += g.y;
            }
        }
        act[nb][0] = v.x; act[nb][1] = v.y;
        act[nb][2] = w.x; act[nb][3] = w.y;
    }
}

__device__ __forceinline__ void store_act16(const float (&act)[8][4],
        float* __restrict__ dst, int wrow, int n, int lane) {
    int tig = lane & 3, grp = lane >> 2;
    int ra = wrow + grp, rb = ra + 8;
#pragma unroll
    for (int nb = 0; nb < 8; nb++) {
        int cw = nb * 4 + tig;
        if (ra < n)
            ((float2*)(dst + (size_t)ra * DD))[cw] = make_float2(act[nb][0], act[nb][1]);
        if (rb < n)
            ((float2*)(dst + (size_t)rb * DD))[cw] = make_float2(act[nb][2], act[nb][3]);
    }
}

// ---- out = relu((in[+add]) @ W1 + B1) @ W2 + B2 ; both weights preloaded once ----
template <bool DO_ADD>
__global__ __launch_bounds__(128, 4)
void mlp2_kernel(const float* __restrict__ in, const float* __restrict__ addv,
                 const float* __restrict__ W1, const float* __restrict__ B1,
                 const float* __restrict__ W2, const float* __restrict__ B2,
                 float* __restrict__ out, int n) {
    __shared__ __align__(16) __nv_bfloat16 wh1[DD * WSTRIDE], wl1[DD * WSTRIDE];
    __shared__ __align__(16) __nv_bfloat16 wh2[DD * WSTRIDE], wl2[DD * WSTRIDE];
    __shared__ float b1s[DD], b2s[DD];

    int tid = threadIdx.x;
    int lane = tid & 31, wid = tid >> 5;
    int wrow = (blockIdx.x * 4 + wid) * 16;

    prep_w(wh1, wl1, W1, tid);
    prep_w(wh2, wl2, W2, tid);
    if (tid < DD) b1s[tid] = B1[tid];
    else if (tid < 2 * DD) b2s[tid - DD] = B2[tid - DD];

    float act[8][4];
    load_act16<DO_ADD>(act, in, addv, wrow, n, lane);
    __syncthreads();

    stage16(act, wh1, wl1, b1s, lane, true);
    stage16(act, wh2, wl2, b2s, lane, false);
    store_act16(act, out, wrow, n, lane);
}

// ---- out = in @ Wf + bf (single stage, no relu) ----
__global__ __launch_bounds__(128, 4)
void final_kernel(const float* __restrict__ in,
                  const float* __restrict__ Wf, const float* __restrict__ bf,
                  float* __restrict__ out, int n) {
    __shared__ __align__(16) __nv_bfloat16 wh[DD * WSTRIDE], wl[DD * WSTRIDE];
    __shared__ float bs[DD];

    int tid = threadIdx.x;
    int lane = tid & 31, wid = tid >> 5;
    int wrow = (blockIdx.x * 4 + wid) * 16;

    prep_w(wh, wl, Wf, tid);
    if (tid < DD) bs[tid] = bf[tid];

    float act[8][4];
    load_act16<false>(act, in, nullptr, wrow, n, lane);
    __syncthreads();

    stage16(act, wh, wl, bs, lane, false);
    store_act16(act, out, wrow, n, lane);
}

// ---------------- gather-side segment sum (validated) ----------------
__global__ __launch_bounds__(256)
void agg_kernel(const float* __restrict__ Msrc, float* __restrict__ G,
                int n, int E) {
    int t = blockIdx.x * blockDim.x + threadIdx.x;
    int w = t >> 5;
    if (w >= n) return;
    int lane = t & 31;
    if (lane == 0) g_cnt[w] = 0;
    int half = lane >> 4;
    int l16 = lane & 15;
    int s = g_rowptr[w] + g_bsums[w >> 10];
    int e = (w == n - 1) ? E : (g_rowptr[w + 1] + g_bsums[(w + 1) >> 10]);
    float a0 = 0.f, a1 = 0.f, a2 = 0.f, a3 = 0.f;
    for (int j = s + half; j < e; j += 2) {
        int c = __ldg(&g_ecol[j]);
        float4 v = __ldg((const float4*)(Msrc + (size_t)c * DD) + l16);
        a0 += v.x; a1 += v.y; a2 += v.z; a3 += v.w;
    }
    a0 += __shfl_down_sync(0xffffffffu, a0, 16);
    a1 += __shfl_down_sync(0xffffffffu, a1, 16);
    a2 += __shfl_down_sync(0xffffffffu, a2, 16);
    a3 += __shfl_down_sync(0xffffffffu, a3, 16);
    if (half == 0)
        ((float4*)(G + (size_t)w * DD))[l16] = make_float4(a0, a1, a2, a3);
}

// ---------------- launch ----------------
extern "C" void kernel_launch(void* const* d_in, const int* in_sizes, int n_in,
                              void* d_out, int out_size) {
    const float* x  = (const float*)d_in[0];
    const int* eidx = (const int*)d_in[1];
    const float* W1 = (const float*)d_in[2];
    const float* b1 = (const float*)d_in[3];
    const float* W2 = (const float*)d_in[4];
    const float* b2 = (const float*)d_in[5];
    const float* Wf = (const float*)d_in[6];
    const float* bf = (const float*)d_in[7];

    int n = in_sizes[0] / DD;
    int E = in_sizes[1] / 2;
    const int* rows = eidx;
    const int* cols = eidx + E;

    float *M, *G, *H, *H2;
    cudaGetSymbolAddress((void**)&M, g_M);
    cudaGetSymbolAddress((void**)&G, g_G);
    cudaGetSymbolAddress((void**)&H, g_H);
    cudaGetSymbolAddress((void**)&H2, g_H2);

    const int TB = 256;
    int nb_e = (E + TB - 1) / TB;
    int nb_scan = (n + 1023) / 1024;
    int nb_mma = (n + 63) / 64;           // 64 rows per block (4 warps x 16)
    int nb_agg = (n * 32 + TB - 1) / TB;

    const float* w1[LL]; const float* bb1[LL];
    const float* w2[LL]; const float* bb2[LL];
    for (int l = 0; l < LL; l++) {
        w1[l] = W1 + l * DD * DD; bb1[l] = b1 + l * DD;
        w2[l] = W2 + l * DD * DD; bb2[l] = b2 + l * DD;
    }

    // CSR build interleaved with first message pass
    hist_kernel<<<nb_e, TB>>>(rows, E);
    scan1_kernel<<<nb_scan, 1024>>>(n);
    mlp2_kernel<false><<<nb_mma, 128>>>(x, nullptr, w1[0], bb1[0], w2[0], bb2[0], M, n);
    scan2_kernel<<<1, 1024>>>(nb_scan);
    scatter_kernel<<<nb_e, TB>>>(rows, cols, E);

    // layer 0
    agg_kernel<<<nb_agg, TB>>>(M, G, n, E);
    mlp2_kernel<true><<<nb_mma, 128>>>(x, G, w1[0], bb1[0], w2[0], bb2[0], H, n);
    // layer 1
    mlp2_kernel<false><<<nb_mma, 128>>>(H, nullptr, w1[1], bb1[1], w2[1], bb2[1], M, n);
    agg_kernel<<<nb_agg, TB>>>(M, G, n, E);
    mlp2_kernel<true><<<nb_mma, 128>>>(H, G, w1[1], bb1[1], w2[1], bb2[1], H2, n);
    // layer 2
    mlp2_kernel<false><<<nb_mma, 128>>>(H2, nullptr, w1[2], bb1[2], w2[2], bb2[2], M, n);
    agg_kernel<<<nb_agg, TB>>>(M, G, n, E);
    mlp2_kernel<true><<<nb_mma, 128>>>(H2, G, w1[2], bb1[2], w2[2], bb2[2], H, n);
    // final projection
    final_kernel<<<nb_mma, 128>>>(H, Wf, bf, (float*)d_out, n);
}

// round 8
// speedup vs baseline: 1.0585x; 1.0585x over previous
#include <cuda_runtime.h>
#include <cuda_bf16.h>

#define DD   64
#define LL   3
#define NMAX 100000
#define EMAX 1200000
#define WSTRIDE 80            // bf16 row stride; 64-bit B loads conflict-free
#define WMAT (DD * WSTRIDE)   // 5120 bf16 per hi or lo matrix

// ---------------- scratch (device globals: allocation-free) ----------------
// g_cnt lifecycle: zero at module load; hist needs cnt==0; scan1 re-zeroes it
// after reading (scatter cursor); agg re-zeroes it for the next graph replay.
__device__ float g_M[NMAX * DD];
__device__ float g_G[NMAX * DD];
__device__ float g_H[NMAX * DD];
__device__ float g_H2[NMAX * DD];
__device__ int   g_cnt[NMAX];
__device__ int   g_rowptr[NMAX];     // within-block exclusive prefix
__device__ int   g_ecol[EMAX];
__device__ int   g_bsums[1024];
// 7 weight matrices (W1[0..2], W2[0..2], Wf), each as [hi | lo] bf16 in B-frag order
__device__ __align__(16) __nv_bfloat16 g_wsp[7 * 2 * WMAT];

// ---------------- CSR construction (validated) ----------------
__global__ void hist_kernel(const int* __restrict__ rows, int E) {
    int e = blockIdx.x * blockDim.x + threadIdx.x;
    if (e < E) atomicAdd(&g_cnt[rows[e]], 1);
}

__global__ void scan1_kernel(int n) {
    __shared__ int sh[1024];
    int i = blockIdx.x * 1024 + threadIdx.x;
    int v = 0;
    if (i < n) { v = g_cnt[i]; g_cnt[i] = 0; }
    sh[threadIdx.x] = v;
    __syncthreads();
    for (int off = 1; off < 1024; off <<= 1) {
        int t = (threadIdx.x >= off) ? sh[threadIdx.x - off] : 0;
        __syncthreads();
        sh[threadIdx.x] += t;
        __syncthreads();
    }
    if (i < n) g_rowptr[i] = sh[threadIdx.x] - v;
    if (threadIdx.x == 1023) g_bsums[blockIdx.x] = sh[1023];
}

__global__ void scan2_kernel(int nb) {
    __shared__ int sh[1024];
    int v = (threadIdx.x < nb) ? g_bsums[threadIdx.x] : 0;
    sh[threadIdx.x] = v;
    __syncthreads();
    for (int off = 1; off < 1024; off <<= 1) {
        int t = (threadIdx.x >= off) ? sh[threadIdx.x - off] : 0;
        __syncthreads();
        sh[threadIdx.x] += t;
        __syncthreads();
    }
    if (threadIdx.x < nb) g_bsums[threadIdx.x] = sh[threadIdx.x] - v;
}

__global__ void scatter_kernel(const int* __restrict__ rows,
                               const int* __restrict__ cols, int E) {
    int e = blockIdx.x * blockDim.x + threadIdx.x;
    if (e < E) {
        int r = rows[e];
        int base = g_rowptr[r] + g_bsums[r >> 10];
        int pos = base + atomicAdd(&g_cnt[r], 1);
        g_ecol[pos] = cols[e];
    }
}

// ---------------- weight prep (once per graph execution) ----------------
// W f32 [k][n] -> bf16 hi/lo split, transposed [n][k] with B-fragment ordering:
// k -> off = kb*16 + tg*4 + hi2*2 + b  (kb=k>>4, r=k&15, tg=(r&7)>>1, b=r&1, hi2=r>>3)
__global__ void prepw_kernel(const float* __restrict__ W1,
                             const float* __restrict__ W2,
                             const float* __restrict__ Wf) {
    int m = blockIdx.x;  // 0..2: W1[l]; 3..5: W2[l]; 6: Wf
    const float* W = (m < 3) ? (W1 + m * DD * DD)
                   : (m < 6) ? (W2 + (m - 3) * DD * DD) : Wf;
    __nv_bfloat16* dst = g_wsp + m * 2 * WMAT;
    for (int idx = threadIdx.x; idx < DD * DD; idx += blockDim.x) {
        int k = idx >> 6, nn = idx & 63;
        int kb = k >> 4, r = k & 15;
        int tg = (r & 7) >> 1, b = r & 1, hi2 = r >> 3;
        int off = nn * WSTRIDE + kb * 16 + tg * 4 + hi2 * 2 + b;
        float w = W[idx];
        __nv_bfloat16 h = __float2bfloat16(w);
        dst[off] = h;
        dst[WMAT + off] = __float2bfloat16(w - __bfloat162float(h));
    }
}

// ---------------- bf16 helpers ----------------
__device__ __forceinline__ unsigned packbf(float lo, float hi) {
    unsigned r;
    asm("cvt.rn.bf16x2.f32 %0, %1, %2;" : "=r"(r) : "f"(hi), "f"(lo));
    return r;
}
__device__ __forceinline__ float lo_f(unsigned u) { return __uint_as_float(u << 16); }
__device__ __forceinline__ float hi_f(unsigned u) { return __uint_as_float(u & 0xffff0000u); }

__device__ __forceinline__ void mma_bf16(float* d,
        unsigned a0, unsigned a1, unsigned a2, unsigned a3,
        unsigned b0, unsigned b1) {
    asm("mma.sync.aligned.m16n8k16.row.col.f32.bf16.bf16.f32 "
        "{%0,%1,%2,%3}, {%4,%5,%6,%7}, {%8,%9}, {%0,%1,%2,%3};"
        : "+f"(d[0]), "+f"(d[1]), "+f"(d[2]), "+f"(d[3])
        : "r"(a0), "r"(a1), "r"(a2), "r"(a3), "r"(b0), "r"(b1));
}

// ---------------- one 32-row GEMM stage on tensor cores ----------------
// act[m][nb][q] C-fragment: rows grp+16m / grp+16m+8, cols nb*8 + 2*tig(+1).
__device__ __forceinline__ void stage32(float (&act)[2][8][4],
        const __nv_bfloat16* ws,   // [hi | lo], WMAT each
        const float* bias, int lane, bool do_relu) {
    int tig = lane & 3, grp = lane >> 2;
    const __nv_bfloat16* wh = ws;
    const __nv_bfloat16* wl = ws + WMAT;
    float acc[2][8][4];
    const float2* bp = (const float2*)bias;
#pragma unroll
    for (int nb = 0; nb < 8; nb++) {
        float2 bv = bp[nb * 4 + tig];
#pragma unroll
        for (int m = 0; m < 2; m++) {
            acc[m][nb][0] = bv.x; acc[m][nb][1] = bv.y;
            acc[m][nb][2] = bv.x; acc[m][nb][3] = bv.y;
        }
    }
#pragma unroll
    for (int kb = 0; kb < 4; kb++) {
        unsigned Ah[2][4], Al[2][4];
#pragma unroll
        for (int m = 0; m < 2; m++) {
            const float* c0 = act[m][2 * kb];
            const float* c1 = act[m][2 * kb + 1];
            Ah[m][0] = packbf(c0[0], c0[1]);
            Ah[m][1] = packbf(c0[2], c0[3]);
            Ah[m][2] = packbf(c1[0], c1[1]);
            Ah[m][3] = packbf(c1[2], c1[3]);
            Al[m][0] = packbf(c0[0] - lo_f(Ah[m][0]), c0[1] - hi_f(Ah[m][0]));
            Al[m][1] = packbf(c0[2] - lo_f(Ah[m][1]), c0[3] - hi_f(Ah[m][1]));
            Al[m][2] = packbf(c1[0] - lo_f(Ah[m][2]), c1[1] - hi_f(Ah[m][2]));
            Al[m][3] = packbf(c1[2] - lo_f(Ah[m][3]), c1[3] - hi_f(Ah[m][3]));
        }
        int woff = kb * 16 + tig * 4;
#pragma unroll
        for (int nb = 0; nb < 8; nb++) {
            int ncol = nb * 8 + grp;
            unsigned long long bh = *(const unsigned long long*)(wh + ncol * WSTRIDE + woff);
            unsigned long long bl = *(const unsigned long long*)(wl + ncol * WSTRIDE + woff);
            unsigned bh0 = (unsigned)bh, bh1 = (unsigned)(bh >> 32);
            unsigned bl0 = (unsigned)bl, bl1 = (unsigned)(bl >> 32);
#pragma unroll
            for (int m = 0; m < 2; m++) {
                mma_bf16(acc[m][nb], Ah[m][0], Ah[m][1], Ah[m][2], Ah[m][3], bh0, bh1);
                mma_bf16(acc[m][nb], Al[m][0], Al[m][1], Al[m][2], Al[m][3], bh0, bh1);
                mma_bf16(acc[m][nb], Ah[m][0], Ah[m][1], Ah[m][2], Ah[m][3], bl0, bl1);
            }
        }
    }
#pragma unroll
    for (int m = 0; m < 2; m++)
#pragma unroll
        for (int nb = 0; nb < 8; nb++)
#pragma unroll
            for (int q = 0; q < 4; q++)
                act[m][nb][q] = do_relu ? fmaxf(acc[m][nb][q], 0.0f) : acc[m][nb][q];
}

// ---- act <-> gmem (row-major [n][64]) in C-fragment layout ----
template <bool DO_ADD>
__device__ __forceinline__ void load_act(float (&act)[2][8][4],
        const float* __restrict__ in, const float* __restrict__ addv,
        int wrow, int n, int lane) {
    int tig = lane & 3, grp = lane >> 2;
#pragma unroll
    for (int m = 0; m < 2; m++) {
        int ra = wrow + m * 16 + grp, rb = ra + 8;
#pragma unroll
        for (int nb = 0; nb < 8; nb++) {
            int cw = nb * 4 + tig;
            float2 v = make_float2(0.f, 0.f), w = make_float2(0.f, 0.f);
            if (ra < n) {
                v = ((const float2*)(in + (size_t)ra * DD))[cw];
                if (DO_ADD) {
                    float2 g = ((const float2*)(addv + (size_t)ra * DD))[cw];
                    v.x += g.x; v.y += g.y;
                }
            }
            if (rb < n) {
                w = ((const float2*)(in + (size_t)rb * DD))[cw];
                if (DO_ADD) {
                    float2 g = ((const float2*)(addv + (size_t)rb * DD))[cw];
                    w.x += g.x; w.y += g.y;
                }
            }
            act[m][nb][0] = v.x; act[m][nb][1] = v.y;
            act[m][nb][2] = w.x; act[m][nb][3] = w.y;
        }
    }
}

__device__ __forceinline__ void store_act(const float (&act)[2][8][4],
        float* __restrict__ dst, int wrow, int n, int lane) {
    int tig = lane & 3, grp = lane >> 2;
#pragma unroll
    for (int m = 0; m < 2; m++) {
        int ra = wrow + m * 16 + grp, rb = ra + 8;
#pragma unroll
        for (int nb = 0; nb < 8; nb++) {
            int cw = nb * 4 + tig;
            if (ra < n)
                ((float2*)(dst + (size_t)ra * DD))[cw] = make_float2(act[m][nb][0], act[m][nb][1]);
            if (rb < n)
                ((float2*)(dst + (size_t)rb * DD))[cw] = make_float2(act[m][nb][2], act[m][nb][3]);
        }
    }
}

// ---- out = relu((in[+add]) @ W1 + B1) @ W2 + B2; split weights preloaded once ----
template <bool DO_ADD>
__global__ __launch_bounds__(128, 3)
void mlp2_kernel(const float* __restrict__ in, const float* __restrict__ addv,
                 int wi1, int wi2,
                 const float* __restrict__ B1, const float* __restrict__ B2,
                 float* __restrict__ out, int n) {
    __shared__ __align__(16) __nv_bfloat16 w1[2 * WMAT];
    __shared__ __align__(16) __nv_bfloat16 w2[2 * WMAT];
    __shared__ float b1s[DD], b2s[DD];

    int tid = threadIdx.x;
    int lane = tid & 31, wid = tid >> 5;
    int wrow = (blockIdx.x * 4 + wid) * 32;

    {   // copy precomputed split weights (bf16, already in B-frag order)
        const uint4* s1 = (const uint4*)(g_wsp + wi1 * 2 * WMAT);
        const uint4* s2 = (const uint4*)(g_wsp + wi2 * 2 * WMAT);
        uint4* d1 = (uint4*)w1;
        uint4* d2 = (uint4*)w2;
#pragma unroll
        for (int i = tid; i < 2 * WMAT / 8; i += 128) {
            d1[i] = s1[i];
            d2[i] = s2[i];
        }
        if (tid < DD) b1s[tid] = B1[tid];
        else if (tid < 2 * DD) b2s[tid - DD] = B2[tid - DD];
    }

    float act[2][8][4];
    load_act<DO_ADD>(act, in, addv, wrow, n, lane);
    __syncthreads();

    stage32(act, w1, b1s, lane, true);
    stage32(act, w2, b2s, lane, false);
    store_act(act, out, wrow, n, lane);
}

// ---- out = in @ Wf + bf (single stage, no relu) ----
__global__ __launch_bounds__(128, 3)
void final_kernel(const float* __restrict__ in, const float* __restrict__ bf,
                  float* __restrict__ out, int n) {
    __shared__ __align__(16) __nv_bfloat16 w[2 * WMAT];
    __shared__ float bs[DD];

    int tid = threadIdx.x;
    int lane = tid & 31, wid = tid >> 5;
    int wrow = (blockIdx.x * 4 + wid) * 32;

    {
        const uint4* s = (const uint4*)(g_wsp + 6 * 2 * WMAT);
        uint4* d = (uint4*)w;
#pragma unroll
        for (int i = tid; i < 2 * WMAT / 8; i += 128) d[i] = s[i];
        if (tid < DD) bs[tid] = bf[tid];
    }

    float act[2][8][4];
    load_act<false>(act, in, nullptr, wrow, n, lane);
    __syncthreads();

    stage32(act, w, bs, lane, false);
    store_act(act, out, wrow, n, lane);
}

// ---------------- gather-side segment sum (validated) ----------------
__global__ __launch_bounds__(256)
void agg_kernel(const float* __restrict__ Msrc, float* __restrict__ G,
                int n, int E) {
    int t = blockIdx.x * blockDim.x + threadIdx.x;
    int w = t >> 5;
    if (w >= n) return;
    int lane = t & 31;
    if (lane == 0) g_cnt[w] = 0;
    int half = lane >> 4;
    int l16 = lane & 15;
    int s = g_rowptr[w] + g_bsums[w >> 10];
    int e = (w == n - 1) ? E : (g_rowptr[w + 1] + g_bsums[(w + 1) >> 10]);
    float a0 = 0.f, a1 = 0.f, a2 = 0.f, a3 = 0.f;
    for (int j = s + half; j < e; j += 2) {
        int c = __ldg(&g_ecol[j]);
        float4 v = __ldg((const float4*)(Msrc + (size_t)c * DD) + l16);
        a0 += v.x; a1 += v.y; a2 += v.z; a3 += v.w;
    }
    a0 += __shfl_down_sync(0xffffffffu, a0, 16);
    a1 += __shfl_down_sync(0xffffffffu, a1, 16);
    a2 += __shfl_down_sync(0xffffffffu, a2, 16);
    a3 += __shfl_down_sync(0xffffffffu, a3, 16);
    if (half == 0)
        ((float4*)(G + (size_t)w * DD))[l16] = make_float4(a0, a1, a2, a3);
}

// ---------------- launch ----------------
extern "C" void kernel_launch(void* const* d_in, const int* in_sizes, int n_in,
                              void* d_out, int out_size) {
    const float* x  = (const float*)d_in[0];
    const int* eidx = (const int*)d_in[1];
    const float* W1 = (const float*)d_in[2];
    const float* b1 = (const float*)d_in[3];
    const float* W2 = (const float*)d_in[4];
    const float* b2 = (const float*)d_in[5];
    const float* Wf = (const float*)d_in[6];
    const float* bf = (const float*)d_in[7];

    int n = in_sizes[0] / DD;
    int E = in_sizes[1] / 2;
    const int* rows = eidx;
    const int* cols = eidx + E;

    float *M, *G, *H, *H2;
    cudaGetSymbolAddress((void**)&M, g_M);
    cudaGetSymbolAddress((void**)&G, g_G);
    cudaGetSymbolAddress((void**)&H, g_H);
    cudaGetSymbolAddress((void**)&H2, g_H2);

    const int TB = 256;
    int nb_e = (E + TB - 1) / TB;
    int nb_scan = (n + 1023) / 1024;
    int nb_mma = (n + 127) / 128;         // 128 rows per block (4 warps x 32)
    int nb_agg = (n * 32 + TB - 1) / TB;

    const float* bb1[LL]; const float* bb2[LL];
    for (int l = 0; l < LL; l++) { bb1[l] = b1 + l * DD; bb2[l] = b2 + l * DD; }

    // weight split prep + CSR build, interleaved with first message pass
    prepw_kernel<<<7, 256>>>(W1, W2, Wf);
    hist_kernel<<<nb_e, TB>>>(rows, E);
    scan1_kernel<<<nb_scan, 1024>>>(n);
    mlp2_kernel<false><<<nb_mma, 128>>>(x, nullptr, 0, 3, bb1[0], bb2[0], M, n);
    scan2_kernel<<<1, 1024>>>(nb_scan);
    scatter_kernel<<<nb_e, TB>>>(rows, cols, E);

    // layer 0
    agg_kernel<<<nb_agg, TB>>>(M, G, n, E);
    mlp2_kernel<true><<<nb_mma, 128>>>(x, G, 0, 3, bb1[0], bb2[0], H, n);
    // layer 1
    mlp2_kernel<false><<<nb_mma, 128>>>(H, nullptr, 1, 4, bb1[1], bb2[1], M, n);
    agg_kernel<<<nb_agg, TB>>>(M, G, n, E);
    mlp2_kernel<true><<<nb_mma, 128>>>(H, G, 1, 4, bb1[1], bb2[1], H2, n);
    // layer 2
    mlp2_kernel<false><<<nb_mma, 128>>>(H2, nullptr, 2, 5, bb1[2], bb2[2], M, n);
    agg_kernel<<<nb_agg, TB>>>(M, G, n, E);
    mlp2_kernel<true><<<nb_mma, 128>>>(H2, G, 2, 5, bb1[2], bb2[2], H, n);
    // final projection
    final_kernel<<<nb_mma, 128>>>(H, bf, (float*)d_out, n);
}

// round 9
// speedup vs baseline: 1.4865x; 1.4043x over previous
#include <cuda_runtime.h>
#include <cuda_bf16.h>

#define DD   64
#define LL   3
#define NMAX 100000
#define EMAX 1200000
#define WSTRIDE 80            // bf16 row stride; 64-bit B loads conflict-free
#define WMAT (DD * WSTRIDE)   // 5120 bf16 per hi or lo matrix

// ---------------- scratch (device globals: allocation-free) ----------------
// g_cnt lifecycle: zero at module load; hist needs cnt==0; scan1 re-zeroes it
// after reading (scatter cursor); agg re-zeroes it for the next graph replay.
__device__ float g_M[NMAX * DD];
__device__ float g_G[NMAX * DD];
__device__ float g_H[NMAX * DD];
__device__ float g_H2[NMAX * DD];
__device__ int   g_cnt[NMAX];
__device__ int   g_rowptr[NMAX];     // within-block exclusive prefix
__device__ int   g_ecol[EMAX];
__device__ int   g_bsums[1024];
// 7 weight matrices (W1[0..2], W2[0..2], Wf), each as [hi | lo] bf16 in B-frag order
__device__ __align__(16) __nv_bfloat16 g_wsp[7 * 2 * WMAT];

// ---------------- CSR construction (validated) ----------------
__global__ void hist_kernel(const int* __restrict__ rows, int E) {
    int e = blockIdx.x * blockDim.x + threadIdx.x;
    if (e < E) atomicAdd(&g_cnt[rows[e]], 1);
}

__global__ void scan1_kernel(int n) {
    __shared__ int sh[1024];
    int i = blockIdx.x * 1024 + threadIdx.x;
    int v = 0;
    if (i < n) { v = g_cnt[i]; g_cnt[i] = 0; }
    sh[threadIdx.x] = v;
    __syncthreads();
    for (int off = 1; off < 1024; off <<= 1) {
        int t = (threadIdx.x >= off) ? sh[threadIdx.x - off] : 0;
        __syncthreads();
        sh[threadIdx.x] += t;
        __syncthreads();
    }
    if (i < n) g_rowptr[i] = sh[threadIdx.x] - v;
    if (threadIdx.x == 1023) g_bsums[blockIdx.x] = sh[1023];
}

__global__ void scan2_kernel(int nb) {
    __shared__ int sh[1024];
    int v = (threadIdx.x < nb) ? g_bsums[threadIdx.x] : 0;
    sh[threadIdx.x] = v;
    __syncthreads();
    for (int off = 1; off < 1024; off <<= 1) {
        int t = (threadIdx.x >= off) ? sh[threadIdx.x - off] : 0;
        __syncthreads();
        sh[threadIdx.x] += t;
        __syncthreads();
    }
    if (threadIdx.x < nb) g_bsums[threadIdx.x] = sh[threadIdx.x] - v;
}

__global__ void scatter_kernel(const int* __restrict__ rows,
                               const int* __restrict__ cols, int E) {
    int e = blockIdx.x * blockDim.x + threadIdx.x;
    if (e < E) {
        int r = rows[e];
        int base = g_rowptr[r] + g_bsums[r >> 10];
        int pos = base + atomicAdd(&g_cnt[r], 1);
        g_ecol[pos] = cols[e];
    }
}

// ---------------- weight prep (once per graph execution) ----------------
// W f32 [k][n] -> bf16 hi/lo split, transposed [n][k] with B-fragment ordering:
// k -> off = kb*16 + tg*4 + hi2*2 + b  (kb=k>>4, r=k&15, tg=(r&7)>>1, b=r&1, hi2=r>>3)
__global__ void prepw_kernel(const float* __restrict__ W1,
                             const float* __restrict__ W2,
                             const float* __restrict__ Wf) {
    int m = blockIdx.x;  // 0..2: W1[l]; 3..5: W2[l]; 6: Wf
    const float* W = (m < 3) ? (W1 + m * DD * DD)
                   : (m < 6) ? (W2 + (m - 3) * DD * DD) : Wf;
    __nv_bfloat16* dst = g_wsp + m * 2 * WMAT;
    for (int idx = threadIdx.x; idx < DD * DD; idx += blockDim.x) {
        int k = idx >> 6, nn = idx & 63;
        int kb = k >> 4, r = k & 15;
        int tg = (r & 7) >> 1, b = r & 1, hi2 = r >> 3;
        int off = nn * WSTRIDE + kb * 16 + tg * 4 + hi2 * 2 + b;
        float w = W[idx];
        __nv_bfloat16 h = __float2bfloat16(w);
        dst[off] = h;
        dst[WMAT + off] = __float2bfloat16(w - __bfloat162float(h));
    }
}

// ---------------- bf16 helpers ----------------
__device__ __forceinline__ unsigned packbf(float lo, float hi) {
    unsigned r;
    asm("cvt.rn.bf16x2.f32 %0, %1, %2;" : "=r"(r) : "f"(hi), "f"(lo));
    return r;
}
__device__ __forceinline__ float lo_f(unsigned u) { return __uint_as_float(u << 16); }
__device__ __forceinline__ float hi_f(unsigned u) { return __uint_as_float(u & 0xffff0000u); }

__device__ __forceinline__ void mma_bf16(float* d,
        unsigned a0, unsigned a1, unsigned a2, unsigned a3,
        unsigned b0, unsigned b1) {
    asm("mma.sync.aligned.m16n8k16.row.col.f32.bf16.bf16.f32 "
        "{%0,%1,%2,%3}, {%4,%5,%6,%7}, {%8,%9}, {%0,%1,%2,%3};"
        : "+f"(d[0]), "+f"(d[1]), "+f"(d[2]), "+f"(d[3])
        : "r"(a0), "r"(a1), "r"(a2), "r"(a3), "r"(b0), "r"(b1));
}

// ---------------- one 16-row GEMM stage on tensor cores (validated R7) ----------
// act[nb][q] C-fragment: rows grp / grp+8 (warp-relative), cols nb*8 + 2*tig(+1).
__device__ __forceinline__ void stage16(float (&act)[8][4],
        const __nv_bfloat16* ws,   // [hi | lo], WMAT each
        const float* bias, int lane, bool do_relu) {
    int tig = lane & 3, grp = lane >> 2;
    const __nv_bfloat16* wh = ws;
    const __nv_bfloat16* wl = ws + WMAT;
    float acc[8][4];
    const float2* bp = (const float2*)bias;
#pragma unroll
    for (int nb = 0; nb < 8; nb++) {
        float2 bv = bp[nb * 4 + tig];
        acc[nb][0] = bv.x; acc[nb][1] = bv.y;
        acc[nb][2] = bv.x; acc[nb][3] = bv.y;
    }
#pragma unroll
    for (int kb = 0; kb < 4; kb++) {
        unsigned Ah[4], Al[4];
        const float* c0 = act[2 * kb];
        const float* c1 = act[2 * kb + 1];
        Ah[0] = packbf(c0[0], c0[1]);
        Ah[1] = packbf(c0[2], c0[3]);
        Ah[2] = packbf(c1[0], c1[1]);
        Ah[3] = packbf(c1[2], c1[3]);
        Al[0] = packbf(c0[0] - lo_f(Ah[0]), c0[1] - hi_f(Ah[0]));
        Al[1] = packbf(c0[2] - lo_f(Ah[1]), c0[3] - hi_f(Ah[1]));
        Al[2] = packbf(c1[0] - lo_f(Ah[2]), c1[1] - hi_f(Ah[2]));
        Al[3] = packbf(c1[2] - lo_f(Ah[3]), c1[3] - hi_f(Ah[3]));
        int woff = kb * 16 + tig * 4;
#pragma unroll
        for (int nb = 0; nb < 8; nb++) {
            int ncol = nb * 8 + grp;
            unsigned long long bh = *(const unsigned long long*)(wh + ncol * WSTRIDE + woff);
            unsigned long long bl = *(const unsigned long long*)(wl + ncol * WSTRIDE + woff);
            unsigned bh0 = (unsigned)bh, bh1 = (unsigned)(bh >> 32);
            unsigned bl0 = (unsigned)bl, bl1 = (unsigned)(bl >> 32);
            mma_bf16(acc[nb], Ah[0], Ah[1], Ah[2], Ah[3], bh0, bh1);
            mma_bf16(acc[nb], Al[0], Al[1], Al[2], Al[3], bh0, bh1);
            mma_bf16(acc[nb], Ah[0], Ah[1], Ah[2], Ah[3], bl0, bl1);
        }
    }
#pragma unroll
    for (int nb = 0; nb < 8; nb++)
#pragma unroll
        for (int q = 0; q < 4; q++)
            act[nb][q] = do_relu ? fmaxf(acc[nb][q], 0.0f) : acc[nb][q];
}

// ---- act <-> gmem (row-major [n][64]) in C-fragment layout ----
template <bool DO_ADD>
__device__ __forceinline__ void load_act16(float (&act)[8][4],
        const float* __restrict__ in, const float* __restrict__ addv,
        int wrow, int n, int lane) {
    int tig = lane & 3, grp = lane >> 2;
    int ra = wrow + grp, rb = ra + 8;
#pragma unroll
    for (int nb = 0; nb < 8; nb++) {
        int cw = nb * 4 + tig;
        float2 v = make_float2(0.f, 0.f), w = make_float2(0.f, 0.f);
        if (ra < n) {
            v = ((const float2*)(in + (size_t)ra * DD))[cw];
            if (DO_ADD) {
                float2 g = ((const float2*)(addv + (size_t)ra * DD))[cw];
                v.x += g.x; v.y += g.y;
            }
        }
        if (rb < n) {
            w = ((const float2*)(in + (size_t)rb * DD))[cw];
            if (DO_ADD) {
                float2 g = ((const float2*)(addv + (size_t)rb * DD))[cw];
                w.x += g.x; w.y += g.y;
            }
        }
        act[nb][0] = v.x; act[nb][1] = v.y;
        act[nb][2] = w.x; act[nb][3] = w.y;
    }
}

__device__ __forceinline__ void store_act16(const float (&act)[8][4],
        float* __restrict__ dst, int wrow, int n, int lane) {
    int tig = lane & 3, grp = lane >> 2;
    int ra = wrow + grp, rb = ra + 8;
#pragma unroll
    for (int nb = 0; nb < 8; nb++) {
        int cw = nb * 4 + tig;
        if (ra < n)
            ((float2*)(dst + (size_t)ra * DD))[cw] = make_float2(act[nb][0], act[nb][1]);
        if (rb < n)
            ((float2*)(dst + (size_t)rb * DD))[cw] = make_float2(act[nb][2], act[nb][3]);
    }
}

// ---- smem weight/bias loaders (bf16 split already precomputed in g_wsp) ----
__device__ __forceinline__ void copy_w(__nv_bfloat16* dst, int wi, int tid, int nthr) {
    const uint4* s = (const uint4*)(g_wsp + wi * 2 * WMAT);
    uint4* d = (uint4*)dst;
    for (int i = tid; i < 2 * WMAT / 8; i += nthr) d[i] = s[i];
}

// ---- out = relu((in[+add]) @ W1 + B1) @ W2 + B2 ----
template <bool DO_ADD>
__global__ __launch_bounds__(256, 2)
void mlp2_kernel(const float* __restrict__ in, const float* __restrict__ addv,
                 int wi1, int wi2,
                 const float* __restrict__ B1, const float* __restrict__ B2,
                 float* __restrict__ out, int n) {
    __shared__ __align__(16) __nv_bfloat16 wA[2 * WMAT], wB[2 * WMAT];
    __shared__ float b1s[DD], b2s[DD];

    int tid = threadIdx.x;
    int lane = tid & 31, wid = tid >> 5;
    int wrow = blockIdx.x * 128 + wid * 16;

    copy_w(wA, wi1, tid, 256);
    copy_w(wB, wi2, tid, 256);
    if (tid < DD) b1s[tid] = B1[tid];
    else if (tid < 2 * DD) b2s[tid - DD] = B2[tid - DD];

    float act[8][4];
    load_act16<DO_ADD>(act, in, addv, wrow, n, lane);
    __syncthreads();

    stage16(act, wA, b1s, lane, true);
    stage16(act, wB, b2s, lane, false);
    store_act16(act, out, wrow, n, lane);
}

// ---- fused: H = mlp_a(in+add); M = mlp_b(H) (4 stages, one act residency) ----
__global__ __launch_bounds__(256, 2)
void fused4_kernel(const float* __restrict__ in, const float* __restrict__ addv,
                   int wa1, int wa2, int wb1, int wb2,
                   const float* __restrict__ Ba1, const float* __restrict__ Ba2,
                   const float* __restrict__ Bb1, const float* __restrict__ Bb2,
                   float* __restrict__ H, float* __restrict__ M, int n) {
    __shared__ __align__(16) __nv_bfloat16 wA[2 * WMAT], wB[2 * WMAT];
    __shared__ float b1s[DD], b2s[DD];

    int tid = threadIdx.x;
    int lane = tid & 31, wid = tid >> 5;
    int wrow = blockIdx.x * 128 + wid * 16;

    copy_w(wA, wa1, tid, 256);
    copy_w(wB, wa2, tid, 256);
    if (tid < DD) b1s[tid] = Ba1[tid];
    else if (tid < 2 * DD) b2s[tid - DD] = Ba2[tid - DD];

    float act[8][4];
    load_act16<true>(act, in, addv, wrow, n, lane);
    __syncthreads();

    stage16(act, wA, b1s, lane, true);
    stage16(act, wB, b2s, lane, false);
    store_act16(act, H, wrow, n, lane);

    __syncthreads();   // all smem reads of pair a done
    copy_w(wA, wb1, tid, 256);
    copy_w(wB, wb2, tid, 256);
    if (tid < DD) b1s[tid] = Bb1[tid];
    else if (tid < 2 * DD) b2s[tid - DD] = Bb2[tid - DD];
    __syncthreads();

    stage16(act, wA, b1s, lane, true);
    stage16(act, wB, b2s, lane, false);
    store_act16(act, M, wrow, n, lane);
}

// ---- fused final: out = (mlp_a(in+add)) @ Wf + bf (3 stages, no intermediate store) ----
__global__ __launch_bounds__(256, 2)
void fused3_kernel(const float* __restrict__ in, const float* __restrict__ addv,
                   int wa1, int wa2,
                   const float* __restrict__ Ba1, const float* __restrict__ Ba2,
                   const float* __restrict__ bf,
                   float* __restrict__ out, int n) {
    __shared__ __align__(16) __nv_bfloat16 wA[2 * WMAT], wB[2 * WMAT];
    __shared__ float b1s[DD], b2s[DD];

    int tid = threadIdx.x;
    int lane = tid & 31, wid = tid >> 5;
    int wrow = blockIdx.x * 128 + wid * 16;

    copy_w(wA, wa1, tid, 256);
    copy_w(wB, wa2, tid, 256);
    if (tid < DD) b1s[tid] = Ba1[tid];
    else if (tid < 2 * DD) b2s[tid - DD] = Ba2[tid - DD];

    float act[8][4];
    load_act16<true>(act, in, addv, wrow, n, lane);
    __syncthreads();

    stage16(act, wA, b1s, lane, true);
    stage16(act, wB, b2s, lane, false);

    __syncthreads();
    copy_w(wA, 6, tid, 256);           // Wf
    if (tid < DD) b1s[tid] = bf[tid];
    __syncthreads();

    stage16(act, wA, b1s, lane, false);
    store_act16(act, out, wrow, n, lane);
}

// ---------------- gather-side segment sum, 2x unrolled ----------------
__global__ __launch_bounds__(256)
void agg_kernel(const float* __restrict__ Msrc, float* __restrict__ G,
                int n, int E) {
    int t = blockIdx.x * blockDim.x + threadIdx.x;
    int w = t >> 5;
    if (w >= n) return;
    int lane = t & 31;
    if (lane == 0) g_cnt[w] = 0;
    int half = lane >> 4;
    int l16 = lane & 15;
    int s = g_rowptr[w] + g_bsums[w >> 10];
    int e = (w == n - 1) ? E : (g_rowptr[w + 1] + g_bsums[(w + 1) >> 10]);
    float a0 = 0.f, a1 = 0.f, a2 = 0.f, a3 = 0.f;
    int j = s + half;
    for (; j + 2 < e; j += 4) {          // two edges in flight per half-warp
        int c0 = __ldg(&g_ecol[j]);
        int c1 = __ldg(&g_ecol[j + 2]);
        float4 v0 = __ldg((const float4*)(Msrc + (size_t)c0 * DD) + l16);
        float4 v1 = __ldg((const float4*)(Msrc + (size_t)c1 * DD) + l16);
        a0 += v0.x + v1.x; a1 += v0.y + v1.y;
        a2 += v0.z + v1.z; a3 += v0.w + v1.w;
    }
    if (j < e) {
        int c = __ldg(&g_ecol[j]);
        float4 v = __ldg((const float4*)(Msrc + (size_t)c * DD) + l16);
        a0 += v.x; a1 += v.y; a2 += v.z; a3 += v.w;
    }
    a0 += __shfl_down_sync(0xffffffffu, a0, 16);
    a1 += __shfl_down_sync(0xffffffffu, a1, 16);
    a2 += __shfl_down_sync(0xffffffffu, a2, 16);
    a3 += __shfl_down_sync(0xffffffffu, a3, 16);
    if (half == 0)
        ((float4*)(G + (size_t)w * DD))[l16] = make_float4(a0, a1, a2, a3);
}

// ---------------- launch ----------------
extern "C" void kernel_launch(void* const* d_in, const int* in_sizes, int n_in,
                              void* d_out, int out_size) {
    const float* x  = (const float*)d_in[0];
    const int* eidx = (const int*)d_in[1];
    const float* W1 = (const float*)d_in[2];
    const float* b1 = (const float*)d_in[3];
    const float* W2 = (const float*)d_in[4];
    const float* b2 = (const float*)d_in[5];
    const float* Wf = (const float*)d_in[6];
    const float* bf = (const float*)d_in[7];

    int n = in_sizes[0] / DD;
    int E = in_sizes[1] / 2;
    const int* rows = eidx;
    const int* cols = eidx + E;

    float *M, *G, *H, *H2;
    cudaGetSymbolAddress((void**)&M, g_M);
    cudaGetSymbolAddress((void**)&G, g_G);
    cudaGetSymbolAddress((void**)&H, g_H);
    cudaGetSymbolAddress((void**)&H2, g_H2);

    const int TB = 256;
    int nb_e = (E + TB - 1) / TB;
    int nb_scan = (n + 1023) / 1024;
    int nb_mma = (n + 127) / 128;         // 128 rows/block (8 warps x 16)
    int nb_agg = (n * 32 + TB - 1) / TB;

    const float* bb1[LL]; const float* bb2[LL];
    for (int l = 0; l < LL; l++) { bb1[l] = b1 + l * DD; bb2[l] = b2 + l * DD; }

    // prep + CSR build; heavy MLP kernel placed 6th for ncu -s 5
    prepw_kernel<<<7, 256>>>(W1, W2, Wf);
    hist_kernel<<<nb_e, TB>>>(rows, E);
    scan1_kernel<<<nb_scan, 1024>>>(n);
    scan2_kernel<<<1, 1024>>>(nb_scan);
    scatter_kernel<<<nb_e, TB>>>(rows, cols, E);

    // M0 = mlp_0(x)
    mlp2_kernel<false><<<nb_mma, 256>>>(x, nullptr, 0, 3, bb1[0], bb2[0], M, n);
    // layer 0: G0 = agg(M0); H1 = mlp_0(x+G0); M1 = mlp_1(H1)
    agg_kernel<<<nb_agg, TB>>>(M, G, n, E);
    fused4_kernel<<<nb_mma, 256>>>(x, G, 0, 3, 1, 4,
                                   bb1[0], bb2[0], bb1[1], bb2[1], H, M, n);
    // layer 1
    agg_kernel<<<nb_agg, TB>>>(M, G, n, E);
    fused4_kernel<<<nb_mma, 256>>>(H, G, 1, 4, 2, 5,
                                   bb1[1], bb2[1], bb1[2], bb2[2], H2, M, n);
    // layer 2 + final projection (no intermediate store)
    agg_kernel<<<nb_agg, TB>>>(M, G, n, E);
    fused3_kernel<<<nb_mma, 256>>>(H2, G, 2, 5, bb1[2], bb2[2], bf,
                                   (float*)d_out, n);
}